// round 8
// baseline (speedup 1.0000x reference)
#include <cuda_runtime.h>

#define NPTS   16384
#define NCHAN  64
#define DX     100
#define DY     88
#define DZ     80
#define PLANE  (DX*DY*DZ)            // 704000 floats per channel plane

#define SHIFT  7                     // 128-element (512B) voxel buckets
#define NBUCK  5500                  // (704000-1)>>7 = 5499
#define NTOT   (2*NBUCK)             // fix histogram + mov histogram

// ---- scratch (static device globals; no allocations) ----
__device__ int   g_hist[NTOT];
__device__ int   g_cursor[NTOT];
__device__ int   g_vox_f[NPTS], g_vox_p[NPTS], g_vox_n[NPTS];
__device__ int   g_sorted_f[NPTS];        // point id, fix-voxel-sorted
__device__ int   g_sorted_m[2*NPTS];      // pid | (neg<<14), mov-voxel-sorted
__device__ float g_fbuf[NPTS*NCHAN];
__device__ float g_pbuf[NPTS*NCHAN];
__device__ float g_nbuf[NPTS*NCHAN];
__device__ float        g_partials[128];
__device__ unsigned int g_count = 0;

__device__ __forceinline__ int redirect(int v, int idx0, int m) {
    int r = (v - idx0) % m;
    return (r < 0) ? r + m : r;
}
__device__ __forceinline__ int voxel_index(const int* __restrict__ pts, int b) {
    const int x = redirect(pts[b*3+0],  25, DX);
    const int y = redirect(pts[b*3+1], 225, DY);
    const int z = redirect(pts[b*3+2],  28, DZ);
    return x*(DY*DZ) + y*DZ + z;
}

// ---- Z: zero histograms ----
__global__ void zero_kernel() {
    for (int i = threadIdx.x; i < NTOT; i += 1024) g_hist[i] = 0;
}

// ---- A: voxel compute + bucket histogram ----
__global__ void __launch_bounds__(256)
index_kernel(const int* __restrict__ fp, const int* __restrict__ pp,
             const int* __restrict__ np_)
{
    const int e = blockIdx.x * 256 + threadIdx.x;   // 0..49151
    const int t = e >> 14;                           // 0=fix 1=pos 2=neg
    const int pid = e & (NPTS - 1);
    const int* pts = (t == 0) ? fp : (t == 1) ? pp : np_;
    const int v = voxel_index(pts, pid);
    if (t == 0) { g_vox_f[pid] = v; atomicAdd(&g_hist[v >> SHIFT], 1); }
    else if (t == 1) { g_vox_p[pid] = v; atomicAdd(&g_hist[NBUCK + (v >> SHIFT)], 1); }
    else { g_vox_n[pid] = v; atomicAdd(&g_hist[NBUCK + (v >> SHIFT)], 1); }
}

// ---- B: exclusive scan of both histograms -> cursors ----
#define SCAN_K 11   // 1024*11 = 11264 >= 11000
__global__ void __launch_bounds__(1024)
scan_kernel()
{
    const int tid = threadIdx.x;
    const int base = tid * SCAN_K;
    int local[SCAN_K];
    int s = 0;
#pragma unroll
    for (int i = 0; i < SCAN_K; i++) {
        const int idx = base + i;
        const int c = (idx < NTOT) ? g_hist[idx] : 0;
        local[i] = s;
        s += c;
    }
    __shared__ int sm[1024];
    sm[tid] = s;
    __syncthreads();
    for (int off = 1; off < 1024; off <<= 1) {
        int v = (tid >= off) ? sm[tid - off] : 0;
        __syncthreads();
        sm[tid] += v;
        __syncthreads();
    }
    const int pre = (tid == 0) ? 0 : sm[tid - 1];
#pragma unroll
    for (int i = 0; i < SCAN_K; i++) {
        const int idx = base + i;
        if (idx < NTOT) {
            int cur = pre + local[i];
            if (idx >= NBUCK) cur -= NPTS;   // mov cursors start at 0
            g_cursor[idx] = cur;
        }
    }
}

// ---- C: scatter into sorted order ----
__global__ void __launch_bounds__(256)
scatter_kernel()
{
    const int e = blockIdx.x * 256 + threadIdx.x;
    const int t = e >> 14;
    const int pid = e & (NPTS - 1);
    if (t == 0) {
        const int v = g_vox_f[pid];
        const int pos = atomicAdd(&g_cursor[v >> SHIFT], 1);
        g_sorted_f[pos] = pid;
    } else if (t == 1) {
        const int v = g_vox_p[pid];
        const int pos = atomicAdd(&g_cursor[NBUCK + (v >> SHIFT)], 1);
        g_sorted_m[pos] = pid;
    } else {
        const int v = g_vox_n[pid];
        const int pos = atomicAdd(&g_cursor[NBUCK + (v >> SHIFT)], 1);
        g_sorted_m[pos] = pid | NPTS;    // bit 14 marks neg
    }
}

// ---- D: sorted gather into compact [B,C] buffers ----
#define DGRID 148
__global__ void __launch_bounds__(256, 1)
gather_kernel(const float* __restrict__ fixf, const float* __restrict__ movf)
{
    for (int e = blockIdx.x * 256 + threadIdx.x; e < 3 * NPTS; e += DGRID * 256) {
        const float* src;
        float* dst;
        int v;
        if (e < NPTS) {
            const int pid = g_sorted_f[e];
            v = g_vox_f[pid];
            src = fixf;
            dst = g_fbuf + pid * NCHAN;
        } else {
            const int code = g_sorted_m[e - NPTS];
            const int pid = code & (NPTS - 1);
            const bool nn = (code & NPTS) != 0;
            v = nn ? g_vox_n[pid] : g_vox_p[pid];
            src = movf;
            dst = (nn ? g_nbuf : g_pbuf) + pid * NCHAN;
        }
        const float* s = src + v;
#pragma unroll
        for (int c = 0; c < NCHAN; c += 4) {
            float4 w;
            w.x = __ldg(s + (c + 0) * PLANE);
            w.y = __ldg(s + (c + 1) * PLANE);
            w.z = __ldg(s + (c + 2) * PLANE);
            w.w = __ldg(s + (c + 3) * PLANE);
            *reinterpret_cast<float4*>(dst + c) = w;
        }
    }
}

// ---- E: streaming loss + deterministic reduction ----
#define EGRID 128
__global__ void __launch_bounds__(256)
loss_kernel(float* __restrict__ out)
{
    const int gtid = blockIdx.x * 256 + threadIdx.x;
    const int b    = gtid >> 1;
    const int half = gtid & 1;

    const float4* F = reinterpret_cast<const float4*>(g_fbuf + b*NCHAN + half*32);
    const float4* P = reinterpret_cast<const float4*>(g_pbuf + b*NCHAN + half*32);
    const float4* N = reinterpret_cast<const float4*>(g_nbuf + b*NCHAN + half*32);

    float dpos = 0.0f, dneg = 0.0f;
#pragma unroll
    for (int i = 0; i < 8; i++) {
        const float4 f = F[i], p = P[i], n = N[i];
        float d;
        d = f.x - p.x; dpos = fmaf(d, d, dpos);
        d = f.y - p.y; dpos = fmaf(d, d, dpos);
        d = f.z - p.z; dpos = fmaf(d, d, dpos);
        d = f.w - p.w; dpos = fmaf(d, d, dpos);
        d = f.x - n.x; dneg = fmaf(d, d, dneg);
        d = f.y - n.y; dneg = fmaf(d, d, dneg);
        d = f.z - n.z; dneg = fmaf(d, d, dneg);
        d = f.w - n.w; dneg = fmaf(d, d, dneg);
    }

    dpos += __shfl_xor_sync(0xffffffffu, dpos, 1);
    dneg += __shfl_xor_sync(0xffffffffu, dneg, 1);

    float loss = 0.0f;
    if (half == 0) {
        const float lp = dpos * dpos;
        float t = fmaxf(1.0f - sqrtf(dneg), 0.0f);   // MARGIN = 1.0
        loss = lp + t * t;
    }
#pragma unroll
    for (int off = 16; off > 0; off >>= 1)
        loss += __shfl_xor_sync(0xffffffffu, loss, off);

    __shared__ float s_loss[8];
    const int warp = threadIdx.x >> 5;
    const int lane = threadIdx.x & 31;
    if (lane == 0) s_loss[warp] = loss;
    __syncthreads();

    __shared__ bool s_last;
    if (threadIdx.x == 0) {
        float acc = 0.0f;
#pragma unroll
        for (int i = 0; i < 8; i++) acc += s_loss[i];
        g_partials[blockIdx.x] = acc;
        __threadfence();
        unsigned int prev = atomicAdd(&g_count, 1u);
        s_last = (prev == EGRID - 1);
    }
    __syncthreads();

    if (s_last) {
        __shared__ float s_red[128];
        if (threadIdx.x < 128) s_red[threadIdx.x] = g_partials[threadIdx.x];
        __syncthreads();
#pragma unroll
        for (int off = 64; off > 0; off >>= 1) {
            if (threadIdx.x < off && threadIdx.x < 128)
                s_red[threadIdx.x] += s_red[threadIdx.x + off];
            __syncthreads();
        }
        if (threadIdx.x == 0) {
            out[0] = s_red[0] * (1000000.0f / (4.0f * (float)NPTS));
            g_count = 0;
        }
    }
}

extern "C" void kernel_launch(void* const* d_in, const int* in_sizes, int n_in,
                              void* d_out, int out_size)
{
    const float* fixf = (const float*)d_in[0];
    const float* movf = (const float*)d_in[1];
    const int*   fp   = (const int*)d_in[2];
    const int*   pp   = (const int*)d_in[3];
    const int*   np_  = (const int*)d_in[4];
    float* out = (float*)d_out;

    zero_kernel   <<<1, 1024>>>();
    index_kernel  <<<192, 256>>>(fp, pp, np_);
    scan_kernel   <<<1, 1024>>>();
    scatter_kernel<<<192, 256>>>();
    gather_kernel <<<DGRID, 256>>>(fixf, movf);
    loss_kernel   <<<EGRID, 256>>>(out);
}

// round 9
// speedup vs baseline: 1.5706x; 1.5706x over previous
#include <cuda_runtime.h>

// Problem constants
#define NPTS   16384
#define NCHAN  64
#define DX     100
#define DY     88
#define DZ     80
#define PLANE  (DX*DY*DZ)          // 704000 floats per channel plane

// 2 threads per point -> 32768 threads = 128 blocks * 256 (single wave)
#define TPB    256
#define GRID   (NPTS * 2 / TPB)    // 128

__device__ float        g_partials[GRID];
__device__ unsigned int g_count = 0;

__device__ __forceinline__ int redirect(int v, int idx0, int m) {
    int r = (v - idx0) % m;
    return (r < 0) ? r + m : r;
}

__device__ __forceinline__ int voxel_index(const int* __restrict__ pts, int b) {
    const int x = redirect(pts[b*3+0],  25, DX);
    const int y = redirect(pts[b*3+1], 225, DY);
    const int z = redirect(pts[b*3+2],  28, DZ);
    return x*(DY*DZ) + y*DZ + z;
}

// L2-only caching load (.cg): bypass L1 allocation. If L1-originated misses
// are what promote L2<-DRAM fills to 128B lines, .cg should fetch 32B sectors
// while still allocating in L2 (preserving the cross-point reuse we rely on).
__device__ __forceinline__ float load_cg(const float* p) {
    float v;
    asm("ld.global.cg.f32 %0, [%1];" : "=f"(v) : "l"(p));
    return v;
}

__global__ void __launch_bounds__(TPB, 1)
ccl_kernel(const float* fixf,
           const float* movf,
           const int*   __restrict__ fp,
           const int*   __restrict__ pp,
           const int*   __restrict__ np_,
           float*       __restrict__ out)
{
    const int tid  = blockIdx.x * TPB + threadIdx.x;
    const int b    = tid >> 1;          // point id
    const int half = tid & 1;           // channel half: 0 -> [0,32), 1 -> [32,64)

    const int fv = voxel_index(fp,  b);
    const int pv = voxel_index(pp,  b);
    const int nv = voxel_index(np_, b);

    const float* pf = fixf + fv + half * 32 * PLANE;
    const float* pq = movf + pv + half * 32 * PLANE;
    const float* pn = movf + nv + half * 32 * PLANE;

    // Chip-wide lockstep channel walk; unroll 8 keeps ~24 loads in flight per
    // thread while the concurrent channel window stays ~16 planes (~59 MB),
    // below L2 capacity for full cross-point line reuse.
    float dpos = 0.0f, dneg = 0.0f;
#pragma unroll 8
    for (int c = 0; c < 32; c++) {
        const float f = load_cg(pf + c * PLANE);
        const float p = load_cg(pq + c * PLANE);
        const float n = load_cg(pn + c * PLANE);
        const float dp = f - p;
        const float dn = f - n;
        dpos = fmaf(dp, dp, dpos);
        dneg = fmaf(dn, dn, dneg);
    }

    // Combine the two channel-halves of this point (adjacent lanes).
    dpos += __shfl_xor_sync(0xffffffffu, dpos, 1);
    dneg += __shfl_xor_sync(0xffffffffu, dneg, 1);

    // Per-point loss on the even lane; odd lane contributes 0.
    float loss = 0.0f;
    if (half == 0) {
        const float lp = dpos * dpos;
        float t = fmaxf(1.0f - sqrtf(dneg), 0.0f);   // MARGIN = 1.0
        loss = lp + t * t;
    }

    // Warp reduce the losses (16 points per warp).
#pragma unroll
    for (int off = 16; off > 0; off >>= 1)
        loss += __shfl_xor_sync(0xffffffffu, loss, off);

    __shared__ float s_loss[TPB / 32];
    const int warp = threadIdx.x >> 5;
    const int lane = threadIdx.x & 31;
    if (lane == 0) s_loss[warp] = loss;
    __syncthreads();

    __shared__ bool s_last;
    if (threadIdx.x == 0) {
        float acc = 0.0f;
#pragma unroll
        for (int i = 0; i < TPB / 32; i++) acc += s_loss[i];
        g_partials[blockIdx.x] = acc;
        __threadfence();
        unsigned int prev = atomicAdd(&g_count, 1u);
        s_last = (prev == GRID - 1);
    }
    __syncthreads();

    if (s_last) {
        // Final deterministic reduction over GRID=128 partials.
        __shared__ float s_red[128];
        if (threadIdx.x < 128) s_red[threadIdx.x] = g_partials[threadIdx.x];
        __syncthreads();
#pragma unroll
        for (int off = 64; off > 0; off >>= 1) {
            if (threadIdx.x < off) s_red[threadIdx.x] += s_red[threadIdx.x + off];
            __syncthreads();
        }
        if (threadIdx.x == 0) {
            // loss = sum / (2 * 2B) * 1e6
            out[0] = s_red[0] * (1000000.0f / (4.0f * (float)NPTS));
            g_count = 0;   // reset for graph replay
        }
    }
}

extern "C" void kernel_launch(void* const* d_in, const int* in_sizes, int n_in,
                              void* d_out, int out_size)
{
    const float* fixf = (const float*)d_in[0];
    const float* movf = (const float*)d_in[1];
    const int*   fp   = (const int*)d_in[2];
    const int*   pp   = (const int*)d_in[3];
    const int*   np_  = (const int*)d_in[4];
    float* out = (float*)d_out;

    ccl_kernel<<<GRID, TPB>>>(fixf, movf, fp, pp, np_, out);
}

// round 10
// speedup vs baseline: 1.5857x; 1.0097x over previous
#include <cuda_runtime.h>

// Problem constants
#define NPTS   16384
#define NCHAN  64
#define DX     100
#define DY     88
#define DZ     80
#define PLANE  (DX*DY*DZ)          // 704000 floats per channel plane

// 2 threads per point -> 32768 threads = 128 blocks * 256 (single wave).
// Converged config: traffic = distinct-128B-line floor (237 MB), BW at the
// random-line DRAM ceiling (~5.55 TB/s). See rounds 3-9 for the sweep.
#define TPB    256
#define GRID   (NPTS * 2 / TPB)    // 128

__device__ float        g_partials[GRID];
__device__ unsigned int g_count = 0;

__device__ __forceinline__ int redirect(int v, int idx0, int m) {
    int r = (v - idx0) % m;
    return (r < 0) ? r + m : r;
}

__device__ __forceinline__ int voxel_index(const int* __restrict__ pts, int b) {
    const int x = redirect(pts[b*3+0],  25, DX);
    const int y = redirect(pts[b*3+1], 225, DY);
    const int z = redirect(pts[b*3+2],  28, DZ);
    return x*(DY*DZ) + y*DZ + z;
}

__global__ void __launch_bounds__(TPB, 1)
ccl_kernel(const float* __restrict__ fixf,
           const float* __restrict__ movf,
           const int*   __restrict__ fp,
           const int*   __restrict__ pp,
           const int*   __restrict__ np_,
           float*       __restrict__ out)
{
    const int tid  = blockIdx.x * TPB + threadIdx.x;
    const int b    = tid >> 1;          // point id
    const int half = tid & 1;           // channel half: 0 -> [0,32), 1 -> [32,64)

    const int fv = voxel_index(fp,  b);
    const int pv = voxel_index(pp,  b);
    const int nv = voxel_index(np_, b);

    const float* __restrict__ pf = fixf + fv + half * 32 * PLANE;
    const float* __restrict__ pq = movf + pv + half * 32 * PLANE;
    const float* __restrict__ pn = movf + nv + half * 32 * PLANE;

    // Chip-wide lockstep channel walk. Unroll 8 -> ~24 independent loads in
    // flight per thread while the concurrent channel window stays ~16 planes
    // (~59 MB) < L2 capacity, giving perfect cross-point line reuse.
    float dpos = 0.0f, dneg = 0.0f;
#pragma unroll 8
    for (int c = 0; c < 32; c++) {
        const float f = __ldg(pf + c * PLANE);
        const float p = __ldg(pq + c * PLANE);
        const float n = __ldg(pn + c * PLANE);
        const float dp = f - p;
        const float dn = f - n;
        dpos = fmaf(dp, dp, dpos);
        dneg = fmaf(dn, dn, dneg);
    }

    // Combine the two channel-halves of this point (adjacent lanes).
    dpos += __shfl_xor_sync(0xffffffffu, dpos, 1);
    dneg += __shfl_xor_sync(0xffffffffu, dneg, 1);

    // Per-point loss, predicated to the even lane (odd lane contributes 0).
    const float lp = dpos * dpos;
    float t = fmaxf(1.0f - sqrtf(dneg), 0.0f);       // MARGIN = 1.0
    float loss = (half == 0) ? (lp + t * t) : 0.0f;

    // Warp reduce the losses (16 points per warp).
#pragma unroll
    for (int off = 16; off > 0; off >>= 1)
        loss += __shfl_xor_sync(0xffffffffu, loss, off);

    __shared__ float s_loss[TPB / 32];
    const int warp = threadIdx.x >> 5;
    const int lane = threadIdx.x & 31;
    if (lane == 0) s_loss[warp] = loss;
    __syncthreads();

    __shared__ bool s_last;
    if (threadIdx.x == 0) {
        float acc = 0.0f;
#pragma unroll
        for (int i = 0; i < TPB / 32; i++) acc += s_loss[i];
        g_partials[blockIdx.x] = acc;
        __threadfence();
        unsigned int prev = atomicAdd(&g_count, 1u);
        s_last = (prev == GRID - 1);
    }
    __syncthreads();

    if (s_last) {
        // Final deterministic reduction over GRID=128 partials.
        __shared__ float s_red[128];
        if (threadIdx.x < 128) s_red[threadIdx.x] = g_partials[threadIdx.x];
        __syncthreads();
#pragma unroll
        for (int off = 64; off > 0; off >>= 1) {
            if (threadIdx.x < off) s_red[threadIdx.x] += s_red[threadIdx.x + off];
            __syncthreads();
        }
        if (threadIdx.x == 0) {
            // loss = sum / (2 * 2B) * 1e6
            out[0] = s_red[0] * (1000000.0f / (4.0f * (float)NPTS));
            g_count = 0;   // reset for graph replay
        }
    }
}

extern "C" void kernel_launch(void* const* d_in, const int* in_sizes, int n_in,
                              void* d_out, int out_size)
{
    const float* fixf = (const float*)d_in[0];
    const float* movf = (const float*)d_in[1];
    const int*   fp   = (const int*)d_in[2];
    const int*   pp   = (const int*)d_in[3];
    const int*   np_  = (const int*)d_in[4];
    float* out = (float*)d_out;

    ccl_kernel<<<GRID, TPB>>>(fixf, movf, fp, pp, np_, out);
}

// round 11
// speedup vs baseline: 1.5869x; 1.0007x over previous
#include <cuda_runtime.h>

// Problem constants
#define NPTS   16384
#define NCHAN  64
#define DX     100
#define DY     88
#define DZ     80
#define PLANE  (DX*DY*DZ)          // 704000 floats per channel plane

// 2 threads per point -> 32768 threads = 128 blocks * 256 (single wave).
// CONVERGED CONFIG (rounds 3-10 sweep):
//   - traffic pinned at distinct-128B-line floor (237 MB; fill granularity is
//     128B regardless of cache operator: .ca == plain == .cg == __ldg)
//   - BW pinned at the random-line DRAM ceiling (~5.6 TB/s), independent of
//     occupancy (12.5%..43%), SM spread (128 vs 148), and request order
//   - channel-lockstep walk keeps concurrent window ~16 planes (~59 MB) < L2,
//     capturing ALL cross-point line reuse (wider windows inflate traffic 28%)
#define TPB    256
#define GRID   (NPTS * 2 / TPB)    // 128

__device__ float        g_partials[GRID];
__device__ unsigned int g_count = 0;

__device__ __forceinline__ int redirect(int v, int idx0, int m) {
    int r = (v - idx0) % m;
    return (r < 0) ? r + m : r;
}

__device__ __forceinline__ int voxel_index(const int* __restrict__ pts, int b) {
    const int x = redirect(pts[b*3+0],  25, DX);
    const int y = redirect(pts[b*3+1], 225, DY);
    const int z = redirect(pts[b*3+2],  28, DZ);
    return x*(DY*DZ) + y*DZ + z;
}

__global__ void __launch_bounds__(TPB, 1)
ccl_kernel(const float* __restrict__ fixf,
           const float* __restrict__ movf,
           const int*   __restrict__ fp,
           const int*   __restrict__ pp,
           const int*   __restrict__ np_,
           float*       __restrict__ out)
{
    const int tid  = blockIdx.x * TPB + threadIdx.x;
    const int b    = tid >> 1;          // point id
    const int half = tid & 1;           // channel half: 0 -> [0,32), 1 -> [32,64)

    const int fv = voxel_index(fp,  b);
    const int pv = voxel_index(pp,  b);
    const int nv = voxel_index(np_, b);

    const float* __restrict__ pf = fixf + fv + half * 32 * PLANE;
    const float* __restrict__ pq = movf + pv + half * 32 * PLANE;
    const float* __restrict__ pn = movf + nv + half * 32 * PLANE;

    // Chip-wide lockstep channel walk; unroll 8 -> ~24 independent loads in
    // flight per thread (MSHR-saturating) with an L2-fitting footprint.
    float dpos = 0.0f, dneg = 0.0f;
#pragma unroll 8
    for (int c = 0; c < 32; c++) {
        const float f = __ldg(pf + c * PLANE);
        const float p = __ldg(pq + c * PLANE);
        const float n = __ldg(pn + c * PLANE);
        const float dp = f - p;
        const float dn = f - n;
        dpos = fmaf(dp, dp, dpos);
        dneg = fmaf(dn, dn, dneg);
    }

    // Combine the two channel-halves of this point (adjacent lanes).
    dpos += __shfl_xor_sync(0xffffffffu, dpos, 1);
    dneg += __shfl_xor_sync(0xffffffffu, dneg, 1);

    // Per-point loss, predicated to the even lane (odd lane contributes 0).
    const float lp = dpos * dpos;
    float t = fmaxf(1.0f - sqrtf(dneg), 0.0f);       // MARGIN = 1.0
    float loss = (half == 0) ? (lp + t * t) : 0.0f;

    // Warp reduce the losses (16 points per warp).
#pragma unroll
    for (int off = 16; off > 0; off >>= 1)
        loss += __shfl_xor_sync(0xffffffffu, loss, off);

    __shared__ float s_loss[TPB / 32];
    const int warp = threadIdx.x >> 5;
    const int lane = threadIdx.x & 31;
    if (lane == 0) s_loss[warp] = loss;
    __syncthreads();

    __shared__ bool s_last;
    if (threadIdx.x == 0) {
        float acc = 0.0f;
#pragma unroll
        for (int i = 0; i < TPB / 32; i++) acc += s_loss[i];
        g_partials[blockIdx.x] = acc;
        __threadfence();
        unsigned int prev = atomicAdd(&g_count, 1u);
        s_last = (prev == GRID - 1);
    }
    __syncthreads();

    if (s_last) {
        // Final deterministic reduction over GRID=128 partials.
        __shared__ float s_red[128];
        if (threadIdx.x < 128) s_red[threadIdx.x] = g_partials[threadIdx.x];
        __syncthreads();
#pragma unroll
        for (int off = 64; off > 0; off >>= 1) {
            if (threadIdx.x < off) s_red[threadIdx.x] += s_red[threadIdx.x + off];
            __syncthreads();
        }
        if (threadIdx.x == 0) {
            // loss = sum / (2 * 2B) * 1e6
            out[0] = s_red[0] * (1000000.0f / (4.0f * (float)NPTS));
            g_count = 0;   // reset for graph replay
        }
    }
}

extern "C" void kernel_launch(void* const* d_in, const int* in_sizes, int n_in,
                              void* d_out, int out_size)
{
    const float* fixf = (const float*)d_in[0];
    const float* movf = (const float*)d_in[1];
    const int*   fp   = (const int*)d_in[2];
    const int*   pp   = (const int*)d_in[3];
    const int*   np_  = (const int*)d_in[4];
    float* out = (float*)d_out;

    ccl_kernel<<<GRID, TPB>>>(fixf, movf, fp, pp, np_, out);
}